// round 17
// baseline (speedup 1.0000x reference)
#include <cuda_runtime.h>
#include <math.h>

#define NB 512   // batch
#define NF 512   // features
#define NS 255   // splits
#define NN 511   // nodes
#define NC 21    // candidates

#define QSCALEF 268435456.0f               // 2^28 (exact exponent shift in fp32)
#define QINV   3.7252902984619140625e-09f  // 2^-28

// ---------------- scratch (no allocations allowed) ----------------
__device__ unsigned long long g_qsplitI[NS * NB]; // [s][b] fixed-point accum (re-zeroed by traj_kernel)
__device__ float g_qnodeT[NN * NB];               // [n][b]
__device__ float g_ga    [NN * NC];
__device__ float g_anode [NN];

// PDL: wait until the preceding kernel's writes are visible
__device__ __forceinline__ void pdl_wait() {
    asm volatile("griddepcontrol.wait;" ::: "memory");
}

// ================= kernel 1: split-K GEMM — occupancy push #2 =================
// R13: full unroll -> 128 regs, 2 blk/SM, 19.3 us. R16: unroll 8, cap 85, 3 blk/SM -> ~15.5 us.
// Now: unroll 4, cap 64 (launch_bounds 256,4) -> 4 blk/SM, 32 warps (100% occ cap).
__global__ __launch_bounds__(256, 4)
void gemm_kernel(const float* __restrict__ x, const float* __restrict__ W)
{
    __shared__ float As[64][68];   // [f][s]
    __shared__ float Bs[64][68];   // [f][b]

    int tid   = threadIdx.x;
    int k0    = blockIdx.x * 64;
    int bBase = blockIdx.y * 64;
    int sBase = blockIdx.z * 64;

    {
        int s = tid & 63, f0 = tid >> 6;
        int gs = sBase + s;
#pragma unroll
        for (int i = 0; i < 16; i++) {
            int f = f0 + i * 4;
            As[f][s] = (gs < NS) ? W[(k0 + f) * NS + gs] : 0.0f;
        }
        int fb = tid & 63, b0 = tid >> 6;
#pragma unroll
        for (int i = 0; i < 16; i++) {
            int b = b0 + i * 4;
            Bs[fb][b] = x[(bBase + b) * NF + k0 + fb];
        }
    }
    __syncthreads();

    int tr = tid >> 4;   // s quad
    int tc = tid & 15;   // b quad
    float acc[4][4];
#pragma unroll
    for (int i = 0; i < 4; i++)
#pragma unroll
        for (int j = 0; j < 4; j++) acc[i][j] = 0.0f;

#pragma unroll 4
    for (int f = 0; f < 64; f++) {
        float4 a4 = *(const float4*)&As[f][tr * 4];
        float4 b4 = *(const float4*)&Bs[f][tc * 4];
        float av[4] = {a4.x, a4.y, a4.z, a4.w};
        float bv[4] = {b4.x, b4.y, b4.z, b4.w};
#pragma unroll
        for (int i = 0; i < 4; i++)
#pragma unroll
            for (int j = 0; j < 4; j++) acc[i][j] += av[i] * bv[j];
    }

#pragma unroll
    for (int i = 0; i < 4; i++) {
        int s = sBase + tr * 4 + i;
        if (s < NS) {
#pragma unroll
            for (int j = 0; j < 4; j++) {
                int b = bBase + tc * 4 + j;
                long long q = __float2ll_rn(acc[i][j] * QSCALEF);   // exact: *2^28 shifts exponent only
                atomicAdd(&g_qsplitI[s * NB + b], (unsigned long long)q);
            }
        }
    }
}

// ================= kernel 2: q_node (ancestor walk) + g_a reduction (FROZEN: R8) =================
__global__ __launch_bounds__(256)
void ga_kernel(const float* __restrict__ bias)
{
    pdl_wait();   // g_qsplitI must be complete

    int n   = blockIdx.x;
    int tid = threadIdx.x;

    float accs[NC];
#pragma unroll
    for (int c = 0; c < NC; c++) accs[c] = 0.0f;

#pragma unroll
    for (int rep = 0; rep < 2; rep++) {
        int b = tid + rep * 256;
        float m = 1.0f;
        int a = n;
        while (a > 0) {
            int p = (a - 1) >> 1;
            float q = (float)(long long)g_qsplitI[p * NB + b] * QINV + bias[p];
            m = fminf(m, (a == 2 * p + 1) ? -q : q);
            a = p;
        }
        g_qnodeT[n * NB + b] = m;
        float qh = m + 0.5f;
#pragma unroll
        for (int c = 0; c < NC; c++) {
            float d = fminf((float)c * (1.0f / 20.0f) - qh, 0.0f);
            accs[c] = fmaf(d, d, accs[c]);
        }
    }

#pragma unroll
    for (int c = 0; c < NC; c++)
#pragma unroll
        for (int o = 16; o > 0; o >>= 1)
            accs[c] += __shfl_down_sync(0xffffffffu, accs[c], o);

    __shared__ float sW[8][NC];
    int w = tid >> 5, l = tid & 31;
    if (l == 0) {
#pragma unroll
        for (int c = 0; c < NC; c++) sW[w][c] = accs[c];
    }
    __syncthreads();
    if (tid < NC) {
        float s = 0.0f;
#pragma unroll
        for (int ww = 0; ww < 8; ww++) s += sW[ww][tid];
        float ac = (float)tid * (1.0f / 20.0f);
        g_ga[n * NC + tid] = 0.5f * ac * ac + 0.5f * s;
    }
}

// ================= kernel 3: the scan (FROZEN: R8) =================
__device__ __forceinline__ float softmin_serial(int g, const float* sGa, const int* sK)
{
    float kg = (float)sK[g];
    int c1 = 2 * g + 1, c2 = 2 * g + 2;
    float k1 = (c1 < NN) ? (float)sK[c1] : 0.0f;
    float k2 = (c2 < NN) ? (float)sK[c2] : 0.0f;
    const float* r0 = &sGa[g * NC];
    const float* r1 = (c1 < NN) ? &sGa[c1 * NC] : r0;
    const float* r2 = (c2 < NN) ? &sGa[c2 * NC] : r0;

    float v[NC];
    float m = -3.0e38f;
#pragma unroll
    for (int c = 0; c < NC; c++) {
        float t = (1.0f - kg) * r0[c] + k1 * r1[c] + k2 * r2[c];
        v[c] = -100.0f * t;
        m = fmaxf(m, v[c]);
    }
    float su = 0.0f, asu = 0.0f;
#pragma unroll
    for (int c = 0; c < NC; c++) {
        float e = __expf(v[c] - m);
        su += e;
        asu += (float)c * (1.0f / 20.0f) * e;
    }
    return asu / su;
}

// order-preserving float -> u32 (exact)
__device__ __forceinline__ unsigned fenc(float f)
{
    unsigned b = __float_as_uint(f);
    return (b & 0x80000000u) ? ~b : (b | 0x80000000u);
}

__global__ __launch_bounds__(256)
void scan_kernel()
{
    __shared__ float sGa[NN * NC];   // 42924 B
    __shared__ float sAgrp[NN];
    __shared__ float sAnode[NN];
    __shared__ int   sK[NN];

    pdl_wait();   // g_ga must be complete

    int tid = threadIdx.x;

    for (int i = tid; i < NN * NC; i += 256) sGa[i] = g_ga[i];
    for (int i = tid; i < NN; i += 256) sK[i] = 0;
    __syncthreads();

    // initial a_grp (k==0 -> own-row softmin); a_node == a_grp initially
    for (int i = tid; i < NN; i += 256) {
        const float* r = &sGa[i * NC];
        float m = -3.0e38f;
#pragma unroll
        for (int c = 0; c < NC; c++) m = fmaxf(m, -100.0f * r[c]);
        float su = 0.0f, asu = 0.0f;
#pragma unroll
        for (int c = 0; c < NC; c++) {
            float e = __expf(-100.0f * r[c] - m);
            su += e; asu += (float)c * (1.0f / 20.0f) * e;
        }
        float ag = asu / su;
        sAgrp[i]  = ag;
        sAnode[i] = ag;
    }
    __syncthreads();

    if (tid < 32) {
        int lane = tid;
        int applied = 0;
        const unsigned THRESH = fenc(1e-8f);
        for (;;) {
            // per-lane best over 16 interleaved nodes (conflict-free LDS, first-index ties)
            float bv = -3.0e38f; int bi = NN;
#pragma unroll
            for (int i = 0; i < 16; i++) {
                int n = i * 32 + lane;
                if (n < NN) {
                    float an = sAnode[n];
                    float ap = (n == 0) ? 1.0f : sAnode[(n - 1) >> 1];
                    float v = an - ap;
                    if (v > bv || (v == bv && n < bi)) { bv = v; bi = n; }
                }
            }
            // exact warp argmax via REDUX: max on encoded value, min index among max-lanes
            unsigned enc  = fenc(bv);
            unsigned vmax = __reduce_max_sync(0xffffffffu, enc);
            unsigned cand = (enc == vmax) ? (unsigned)bi : 0xffffffffu;
            unsigned gbi  = __reduce_min_sync(0xffffffffu, cand);
            int t = (vmax <= THRESH && gbi > 0u) ? (int)gbi : -1;

            if (t < 0 || applied >= NN) break;   // fixed point / 512th body's merge discarded
            applied++;
            if (lane == 0) sK[t] += 1;
            __syncwarp();

            int p = (t - 1) >> 1;
            float na = 0.0f;
            if (lane < 2) na = softmin_serial(lane == 0 ? p : t, sGa, sK);
            if (lane == 0) sAgrp[p] = na;
            else if (lane == 1) sAgrp[t] = na;
            __syncwarp();

            // incremental a_node refresh: exactly {p, t, sib(t), 2t+1, 2t+2}
            if (lane < 5) {
                int s0 = 2 * p + 1, s1 = 2 * p + 2;
                int sib = (s0 == t) ? s1 : s0;
                int m = (lane == 0) ? p : (lane == 1) ? t : (lane == 2) ? sib
                      : (lane == 3) ? 2 * t + 1 : 2 * t + 2;
                if (m < NN) {
                    float an;
                    if (m == 0) an = sAgrp[0];
                    else {
                        float k = (float)sK[m];
                        an = (1.0f - k) * sAgrp[m] + k * sAgrp[(m - 1) >> 1];
                    }
                    sAnode[m] = an;
                }
            }
            __syncwarp();
        }
    }
    __syncthreads();

    for (int i = tid; i < NN; i += 256) g_anode[i] = sAnode[i];
}

// ================= kernel 4: transposed trajectory + distributed re-zero (FROZEN: R8) ====
__global__ __launch_bounds__(256)
void traj_kernel(float* __restrict__ out)
{
    __shared__ float tile[32][33];

    pdl_wait();   // g_anode / g_qnodeT must be complete

    int tid = threadIdx.x;
    int tn = blockIdx.x >> 4, tb = blockIdx.x & 15;
    int n0 = tn * 32, b0 = tb * 32;

#pragma unroll
    for (int pass = 0; pass < 4; pass++) {
        int r = (tid >> 5) + pass * 8, c = tid & 31;
        int n = n0 + r;
        float v = 0.0f;
        if (n < NN) {
            float q = g_qnodeT[n * NB + b0 + c];          // coalesced over b
            v = fminf(fmaxf(q, 0.0f), g_anode[n]);
        }
        tile[r][c] = v;
    }
    __syncthreads();
#pragma unroll
    for (int pass = 0; pass < 4; pass++) {
        int r = (tid >> 5) + pass * 8, c = tid & 31;
        int n = n0 + c;
        if (n < NN) out[(b0 + r) * NN + n] = tile[c][r];  // coalesced over n
    }

    // re-zero fixed-point accumulator for next launch, spread over 256 blocks
    ulonglong2 z; z.x = 0ULL; z.y = 0ULL;
    ulonglong2* p = (ulonglong2*)g_qsplitI;
    for (int i = blockIdx.x * 256 + tid; i < NS * NB / 2; i += 256 * 256) p[i] = z;
}

// ---------------- launch (PDL on the three dependent kernels) ----------------
extern "C" void kernel_launch(void* const* d_in, const int* in_sizes, int n_in,
                              void* d_out, int out_size)
{
    const float* x = (const float*)d_in[0];
    const float* W = (const float*)d_in[1];
    const float* b = (const float*)d_in[2];
    // d_in[3] = max_depth (fixed at 8; shapes hardcoded)

    gemm_kernel<<<dim3(8, 8, 4), 256>>>(x, W);

    cudaLaunchAttribute attr[1];
    attr[0].id = cudaLaunchAttributeProgrammaticStreamSerialization;
    attr[0].val.programmaticStreamSerializationAllowed = 1;

    cudaLaunchConfig_t cfg = {};
    cfg.attrs = attr;
    cfg.numAttrs = 1;
    cfg.stream = 0;

    cfg.gridDim = dim3(NN); cfg.blockDim = dim3(256);
    cudaLaunchKernelEx(&cfg, ga_kernel, b);

    cfg.gridDim = dim3(1); cfg.blockDim = dim3(256);
    cudaLaunchKernelEx(&cfg, scan_kernel);

    cfg.gridDim = dim3(256); cfg.blockDim = dim3(256);
    cudaLaunchKernelEx(&cfg, traj_kernel, (float*)d_out);
}